// round 2
// baseline (speedup 1.0000x reference)
#include <cuda_runtime.h>
#include <cuda_bf16.h>
#include <math.h>

// Problem constants
#define HT   128          // target H = W
#define HIN  64
#define CC   256          // channels
#define FF   128          // proj filters
#define BB   4            // batch
#define NU   32           // MLP units
#define DIN  118
#define KK2  9            // 3x3 taps
#define NOUT 2304         // C*K*K

#define PIF  3.14159265358979323846f

// Scratch (device globals: allocation-free rule)
__device__ float g_ker[(size_t)HT * HT * NOUT];          // [h][w][t][c]  ~151 MB
__device__ float g_y[(size_t)BB * HT * HT * CC];         // [b][h][w][c]  ~67 MB

// ---------------------------------------------------------------------------
// K1: hypernetwork. 1024 CTAs x 256 thr; CTA handles 16 pixels (row-major).
// ---------------------------------------------------------------------------
__global__ __launch_bounds__(256) void hyper_kernel(
    const float* __restrict__ W1, const float* __restrict__ b1,
    const float* __restrict__ W2, const float* __restrict__ b2,
    const float* __restrict__ W3, const float* __restrict__ b3,
    const float* __restrict__ W4, const float* __restrict__ b4,
    const float* __restrict__ Wo, const float* __restrict__ bo)
{
    __shared__ float feat[16][120];
    __shared__ float xa[16][32];
    __shared__ float xb[16][32];
    __shared__ float x4t[32][16];   // transposed final hidden layer

    const int tid  = threadIdx.x;
    const int pix0 = blockIdx.x * 16;

    // ---- features ----
    for (int idx = tid; idx < 16 * DIN; idx += 256) {
        int p  = idx / DIN;
        int fi = idx - p * DIN;
        int pix = pix0 + p;
        int h = pix >> 7, w = pix & 127;
        float v;
        if (fi < 50) {
            int i   = (fi < 25) ? fi : fi - 25;
            float x = ((fi < 25) ? (float)h : (float)w) * (1.0f / 127.0f);
            float f = 1.0f + (float)i * (1.0f / 24.0f);
            v = cosf(PIF * (2.0f * x + 1.0f) * f);
        } else if (fi < 100) {
            int i   = (fi - 50) % 25;
            float f = 1.0f + (float)i * (1.0f / 24.0f);
            v = cosf(PIF * 5.0f * f);             // scale coords are both 2.0
        } else {
            v = -1.0f;                             // kernel_enc is exactly -1
        }
        feat[p][fi] = v;
    }
    __syncthreads();

    // ---- layer 1: 118 -> 32 ----
    for (int o = tid; o < 16 * NU; o += 256) {
        int p = o >> 5, j = o & 31;
        float s = b1[j];
        #pragma unroll 2
        for (int k = 0; k < DIN; ++k) s += feat[p][k] * W1[k * NU + j];
        xa[p][j] = fmaxf(s, 0.0f);
    }
    __syncthreads();

    // ---- layer 2 ----
    for (int o = tid; o < 16 * NU; o += 256) {
        int p = o >> 5, j = o & 31;
        float s = b2[j];
        #pragma unroll
        for (int k = 0; k < NU; ++k) s += xa[p][k] * W2[k * NU + j];
        xb[p][j] = fmaxf(s, 0.0f);
    }
    __syncthreads();

    // ---- layer 3 ----
    for (int o = tid; o < 16 * NU; o += 256) {
        int p = o >> 5, j = o & 31;
        float s = b3[j];
        #pragma unroll
        for (int k = 0; k < NU; ++k) s += xb[p][k] * W3[k * NU + j];
        xa[p][j] = fmaxf(s, 0.0f);
    }
    __syncthreads();

    // ---- layer 4 (store transposed) ----
    for (int o = tid; o < 16 * NU; o += 256) {
        int p = o >> 5, j = o & 31;
        float s = b4[j];
        #pragma unroll
        for (int k = 0; k < NU; ++k) s += xa[p][k] * W4[k * NU + j];
        x4t[j][p] = fmaxf(s, 0.0f);
    }
    __syncthreads();

    // ---- output layer: [16 x 32] @ [32 x 2304] ----
    // thread tid owns channel c = tid; loops t = 0..8 (j = t*256 + c)
    const int c = tid;
    for (int t = 0; t < 9; ++t) {
        const int j = t * CC + c;
        float acc[16];
        const float bj = bo[j];
        #pragma unroll
        for (int p = 0; p < 16; ++p) acc[p] = bj;

        #pragma unroll 4
        for (int kk = 0; kk < NU; ++kk) {
            float wv = Wo[kk * NOUT + j];
            const float4* xv = (const float4*)&x4t[kk][0];
            #pragma unroll
            for (int q = 0; q < 4; ++q) {
                float4 x4 = xv[q];
                acc[q * 4 + 0] += x4.x * wv;
                acc[q * 4 + 1] += x4.y * wv;
                acc[q * 4 + 2] += x4.z * wv;
                acc[q * 4 + 3] += x4.w * wv;
            }
        }
        #pragma unroll
        for (int p = 0; p < 16; ++p)
            g_ker[(size_t)(pix0 + p) * NOUT + j] = acc[p];
    }
}

// ---------------------------------------------------------------------------
// K2: per-pixel 3x3 weighted patch sum on nearest-upsampled input.
// grid = 16384 (one pixel), 256 threads (one channel each), all 4 batches.
// ---------------------------------------------------------------------------
__global__ __launch_bounds__(256) void conv_kernel(const float* __restrict__ main_in)
{
    const int pix = blockIdx.x;
    const int c   = threadIdx.x;
    const int h   = pix >> 7, w = pix & 127;

    float kv[9];
    const float* kp = &g_ker[(size_t)pix * NOUT + c];
    #pragma unroll
    for (int t = 0; t < 9; ++t) kv[t] = kp[t * CC];

    #pragma unroll
    for (int b = 0; b < BB; ++b) {
        float y = 0.0f;
        #pragma unroll
        for (int di = 0; di < 3; ++di) {
            int hh = h + di - 1;
            if ((unsigned)hh < (unsigned)HT) {
                int sr = hh >> 1;
                const float* rowp = main_in + (((size_t)b * HIN + sr) * HIN) * CC + c;
                #pragma unroll
                for (int dj = 0; dj < 3; ++dj) {
                    int ww = w + dj - 1;
                    if ((unsigned)ww < (unsigned)HT)
                        y += rowp[(size_t)(ww >> 1) * CC] * kv[di * 3 + dj];
                }
            }
        }
        g_y[(((size_t)b * HT + h) * HT + w) * CC + c] = y;
    }
}

// ---------------------------------------------------------------------------
// K3: projection GEMM. C[M=65536, N=128] = Y[M,256] @ Wp[256,128] + b_proj
// 128x128 CTA tile, 8x8 per thread, BK=16.
// ---------------------------------------------------------------------------
#define BM 128
#define BN 128
#define BK 16

__global__ __launch_bounds__(256) void proj_gemm(
    const float* __restrict__ Wp, const float* __restrict__ bproj,
    float* __restrict__ out)
{
    __shared__ float As[BK][BM + 4];   // transposed A tile (+pad)
    __shared__ float Bs[BK][BN];

    const int tid = threadIdx.x;
    const int m0  = blockIdx.x * BM;
    const int tx  = tid & 15;           // N sub-tile
    const int ty  = tid >> 4;           // M sub-tile

    // A load mapping: 2 float4 per thread
    const int arow = tid >> 2;          // 0..63
    const int acol = (tid & 3) * 4;     // 0,4,8,12
    // B load mapping: 2 float4 per thread
    const int brow = tid >> 5;          // 0..7
    const int bcol = (tid & 31) * 4;    // 0..124

    float acc[8][8];
    #pragma unroll
    for (int i = 0; i < 8; ++i)
        #pragma unroll
        for (int j = 0; j < 8; ++j) acc[i][j] = 0.0f;

    const float* Y = g_y;

    for (int k0 = 0; k0 < CC; k0 += BK) {
        float4 a0 = *(const float4*)&Y[(size_t)(m0 + arow)      * CC + k0 + acol];
        float4 a1 = *(const float4*)&Y[(size_t)(m0 + arow + 64) * CC + k0 + acol];
        float4 bv0 = *(const float4*)&Wp[(size_t)(k0 + brow)     * FF + bcol];
        float4 bv1 = *(const float4*)&Wp[(size_t)(k0 + brow + 8) * FF + bcol];

        if (k0) __syncthreads();
        As[acol + 0][arow]      = a0.x;
        As[acol + 1][arow]      = a0.y;
        As[acol + 2][arow]      = a0.z;
        As[acol + 3][arow]      = a0.w;
        As[acol + 0][arow + 64] = a1.x;
        As[acol + 1][arow + 64] = a1.y;
        As[acol + 2][arow + 64] = a1.z;
        As[acol + 3][arow + 64] = a1.w;
        *(float4*)&Bs[brow][bcol]     = bv0;
        *(float4*)&Bs[brow + 8][bcol] = bv1;
        __syncthreads();

        #pragma unroll
        for (int k = 0; k < BK; ++k) {
            float4 av0 = *(const float4*)&As[k][ty * 8];
            float4 av1 = *(const float4*)&As[k][ty * 8 + 4];
            float4 bw0 = *(const float4*)&Bs[k][tx * 8];
            float4 bw1 = *(const float4*)&Bs[k][tx * 8 + 4];
            float a[8] = {av0.x, av0.y, av0.z, av0.w, av1.x, av1.y, av1.z, av1.w};
            float b[8] = {bw0.x, bw0.y, bw0.z, bw0.w, bw1.x, bw1.y, bw1.z, bw1.w};
            #pragma unroll
            for (int i = 0; i < 8; ++i)
                #pragma unroll
                for (int j = 0; j < 8; ++j)
                    acc[i][j] += a[i] * b[j];
        }
    }

    // epilogue
    #pragma unroll
    for (int i = 0; i < 8; ++i) {
        const size_t m = (size_t)(m0 + ty * 8 + i);
        #pragma unroll
        for (int j = 0; j < 8; j += 4) {
            int n = tx * 8 + j;
            float4 r;
            r.x = acc[i][j + 0] + bproj[n + 0];
            r.y = acc[i][j + 1] + bproj[n + 1];
            r.z = acc[i][j + 2] + bproj[n + 2];
            r.w = acc[i][j + 3] + bproj[n + 3];
            *(float4*)&out[m * FF + n] = r;
        }
    }
}

// ---------------------------------------------------------------------------
extern "C" void kernel_launch(void* const* d_in, const int* in_sizes, int n_in,
                              void* d_out, int out_size)
{
    const float* main_in = (const float*)d_in[0];
    // d_in[1] = skip_connection (shape-only, unused)
    const float* W1 = (const float*)d_in[2];
    const float* b1 = (const float*)d_in[3];
    const float* W2 = (const float*)d_in[4];
    const float* b2 = (const float*)d_in[5];
    const float* W3 = (const float*)d_in[6];
    const float* b3 = (const float*)d_in[7];
    const float* W4 = (const float*)d_in[8];
    const float* b4 = (const float*)d_in[9];
    const float* Wo = (const float*)d_in[10];
    const float* bo = (const float*)d_in[11];
    const float* Wp = (const float*)d_in[12];
    const float* bp = (const float*)d_in[13];
    float* out = (float*)d_out;

    hyper_kernel<<<1024, 256>>>(W1, b1, W2, b2, W3, b3, W4, b4, Wo, bo);
    conv_kernel<<<HT * HT, 256>>>(main_in);
    proj_gemm<<<(BB * HT * HT) / BM, 256>>>(Wp, bp, out);
}

// round 4
// speedup vs baseline: 1.6199x; 1.6199x over previous
#include <cuda_runtime.h>
#include <cuda_bf16.h>
#include <cstdint>
#include <math.h>

#define HT   128
#define CC   256
#define FF   128
#define BB   4
#define NU   32
#define DIN  118
#define NOUT 2304
#define PIF  3.14159265358979323846f

typedef __nv_bfloat16 bf16;

// ---------------- scratch globals ----------------
__device__ __align__(16) bf16  g_x4h[(size_t)16384 * 32];
__device__ __align__(16) bf16  g_x4l[(size_t)16384 * 32];
__device__ __align__(16) bf16  g_WoTh[(size_t)NOUT * 32];   // [n][k]
__device__ __align__(16) bf16  g_WoTl[(size_t)NOUT * 32];
__device__ __align__(16) bf16  g_WpTh[(size_t)FF * CC];     // [n][k]
__device__ __align__(16) bf16  g_WpTl[(size_t)FF * CC];
__device__ __align__(16) float g_ker[(size_t)16384 * NOUT]; // 151 MB
__device__ __align__(16) bf16  g_yh[(size_t)65536 * CC];
__device__ __align__(16) bf16  g_yl[(size_t)65536 * CC];

__device__ __forceinline__ void split_bf(float v, bf16& hi, bf16& lo) {
    hi = __float2bfloat16(v);
    lo = __float2bfloat16(v - __bfloat162float(hi));
}

__device__ __forceinline__ void mma16816(float c[4], const uint32_t a[4], const uint32_t b[2]) {
    asm volatile(
        "mma.sync.aligned.m16n8k16.row.col.f32.bf16.bf16.f32 "
        "{%0,%1,%2,%3}, {%4,%5,%6,%7}, {%8,%9}, {%0,%1,%2,%3};"
        : "+f"(c[0]), "+f"(c[1]), "+f"(c[2]), "+f"(c[3])
        : "r"(a[0]), "r"(a[1]), "r"(a[2]), "r"(a[3]), "r"(b[0]), "r"(b[1]));
}

// ---------------------------------------------------------------------------
// prep: Wo^T, Wp^T -> bf16 hi/lo, n-major
// ---------------------------------------------------------------------------
__global__ __launch_bounds__(256) void prep_kernel(const float* __restrict__ Wo,
                                                   const float* __restrict__ Wp)
{
    int idx = blockIdx.x * 256 + threadIdx.x;
    if (idx < NOUT * 32) {
        int n = idx >> 5, k = idx & 31;
        bf16 hi, lo; split_bf(Wo[(size_t)k * NOUT + n], hi, lo);
        g_WoTh[idx] = hi; g_WoTl[idx] = lo;
    } else if ((idx -= NOUT * 32) < FF * CC) {
        int n = idx >> 8, k = idx & 255;
        bf16 hi, lo; split_bf(Wp[(size_t)k * FF + n], hi, lo);
        g_WpTh[idx] = hi; g_WpTl[idx] = lo;
    }
}

// ---------------------------------------------------------------------------
// mlp: features + layers 1-4 -> x4 (bf16 hi/lo, row-major [pix][32])
// ---------------------------------------------------------------------------
__global__ __launch_bounds__(256) void mlp_kernel(
    const float* __restrict__ W1, const float* __restrict__ b1,
    const float* __restrict__ W2, const float* __restrict__ b2,
    const float* __restrict__ W3, const float* __restrict__ b3,
    const float* __restrict__ W4, const float* __restrict__ b4)
{
    __shared__ float feat[16][120];
    __shared__ float xa[16][32];
    __shared__ float xb[16][32];
    const int tid = threadIdx.x;
    const int pix0 = blockIdx.x * 16;

    for (int idx = tid; idx < 16 * DIN; idx += 256) {
        int p = idx / DIN, fi = idx - p * DIN;
        int pix = pix0 + p, h = pix >> 7, w = pix & 127;
        float v;
        if (fi < 50) {
            int i = (fi < 25) ? fi : fi - 25;
            float x = ((fi < 25) ? (float)h : (float)w) * (1.0f / 127.0f);
            float f = 1.0f + (float)i * (1.0f / 24.0f);
            v = cosf(PIF * (2.0f * x + 1.0f) * f);
        } else if (fi < 100) {
            float f = 1.0f + (float)((fi - 50) % 25) * (1.0f / 24.0f);
            v = cosf(PIF * 5.0f * f);
        } else v = -1.0f;
        feat[p][fi] = v;
    }
    __syncthreads();
    for (int o = tid; o < 512; o += 256) {
        int p = o >> 5, j = o & 31;
        float s = b1[j];
        for (int k = 0; k < DIN; ++k) s += feat[p][k] * W1[k * NU + j];
        xa[p][j] = fmaxf(s, 0.0f);
    }
    __syncthreads();
    for (int o = tid; o < 512; o += 256) {
        int p = o >> 5, j = o & 31;
        float s = b2[j];
        #pragma unroll
        for (int k = 0; k < NU; ++k) s += xa[p][k] * W2[k * NU + j];
        xb[p][j] = fmaxf(s, 0.0f);
    }
    __syncthreads();
    for (int o = tid; o < 512; o += 256) {
        int p = o >> 5, j = o & 31;
        float s = b3[j];
        #pragma unroll
        for (int k = 0; k < NU; ++k) s += xb[p][k] * W3[k * NU + j];
        xa[p][j] = fmaxf(s, 0.0f);
    }
    __syncthreads();
    for (int o = tid; o < 512; o += 256) {
        int p = o >> 5, j = o & 31;
        float s = b4[j];
        #pragma unroll
        for (int k = 0; k < NU; ++k) s += xa[p][k] * W4[k * NU + j];
        float v = fmaxf(s, 0.0f);
        bf16 hi, lo; split_bf(v, hi, lo);
        size_t o2 = (size_t)(pix0 + p) * 32 + j;
        g_x4h[o2] = hi; g_x4l[o2] = lo;
    }
}

// ---------------------------------------------------------------------------
// gemm1: g_ker[16384,2304] = x4 @ Wo^T' + bo   (mma.sync bf16, split, K=32)
// grid (128, 18); 256 thr = 8 warps (4m x 2n); CTA tile 128x128
// SMEM row stride 72 bf16 (h cols 0..31, l cols 32..63)
// ---------------------------------------------------------------------------
__global__ __launch_bounds__(256) void gemm1_kernel(const float* __restrict__ bo)
{
    __shared__ __align__(16) bf16 As[128 * 72];
    __shared__ __align__(16) bf16 Bs[128 * 72];

    const int tid = threadIdx.x;
    const int wid = tid >> 5, lane = tid & 31;
    const int gid = lane >> 2, tig = lane & 3;
    const int m0 = blockIdx.x * 128, n0g = blockIdx.y * 128;
    const int wm0 = (wid & 3) * 32, wn0 = (wid >> 2) * 64;

    // load tiles: 128 rows x 4 uint4 per plane
    for (int i = tid; i < 512; i += 256) {
        int r = i >> 2, q = (i & 3) * 8;
        *(uint4*)&As[r * 72 + q]      = *(const uint4*)&g_x4h[(size_t)(m0 + r) * 32 + q];
        *(uint4*)&As[r * 72 + 32 + q] = *(const uint4*)&g_x4l[(size_t)(m0 + r) * 32 + q];
        *(uint4*)&Bs[r * 72 + q]      = *(const uint4*)&g_WoTh[(size_t)(n0g + r) * 32 + q];
        *(uint4*)&Bs[r * 72 + 32 + q] = *(const uint4*)&g_WoTl[(size_t)(n0g + r) * 32 + q];
    }
    __syncthreads();

    float c[2][8][4];
    #pragma unroll
    for (int i = 0; i < 2; ++i)
        #pragma unroll
        for (int j = 0; j < 8; ++j)
            #pragma unroll
            for (int e = 0; e < 4; ++e) c[i][j][e] = 0.0f;

    #pragma unroll
    for (int combo = 0; combo < 3; ++combo) {
        const int aoff = (combo == 2) ? 32 : 0;
        const int boff = (combo == 1) ? 32 : 0;
        #pragma unroll
        for (int ks = 0; ks < 2; ++ks) {
            const int kb = ks * 16;
            uint32_t a[2][4];
            #pragma unroll
            for (int mf = 0; mf < 2; ++mf) {
                int row = wm0 + mf * 16 + gid;
                a[mf][0] = *(const uint32_t*)&As[row * 72       + aoff + kb + tig * 2];
                a[mf][1] = *(const uint32_t*)&As[(row + 8) * 72 + aoff + kb + tig * 2];
                a[mf][2] = *(const uint32_t*)&As[row * 72       + aoff + kb + tig * 2 + 8];
                a[mf][3] = *(const uint32_t*)&As[(row + 8) * 72 + aoff + kb + tig * 2 + 8];
            }
            uint32_t b[8][2];
            #pragma unroll
            for (int nf = 0; nf < 8; ++nf) {
                int n = wn0 + nf * 8 + gid;
                b[nf][0] = *(const uint32_t*)&Bs[n * 72 + boff + kb + tig * 2];
                b[nf][1] = *(const uint32_t*)&Bs[n * 72 + boff + kb + tig * 2 + 8];
            }
            #pragma unroll
            for (int mf = 0; mf < 2; ++mf)
                #pragma unroll
                for (int nf = 0; nf < 8; ++nf)
                    mma16816(c[mf][nf], a[mf], b[nf]);
        }
    }

    // epilogue
    #pragma unroll
    for (int mf = 0; mf < 2; ++mf) {
        int gm = m0 + wm0 + mf * 16 + gid;
        #pragma unroll
        for (int nf = 0; nf < 8; ++nf) {
            int gn = n0g + wn0 + nf * 8 + tig * 2;
            float bx = __ldg(&bo[gn]), by = __ldg(&bo[gn + 1]);
            float2 v0 = { c[mf][nf][0] + bx, c[mf][nf][1] + by };
            float2 v1 = { c[mf][nf][2] + bx, c[mf][nf][3] + by };
            *(float2*)&g_ker[(size_t)gm * NOUT + gn]       = v0;
            *(float2*)&g_ker[(size_t)(gm + 8) * NOUT + gn] = v1;
        }
    }
}

// ---------------------------------------------------------------------------
// conv: 3x3 weighted patch sum -> y bf16 hi/lo (row-major [m][256])
// ---------------------------------------------------------------------------
__global__ __launch_bounds__(256) void conv_kernel(const float* __restrict__ main_in)
{
    const int pix = blockIdx.x, cth = threadIdx.x;
    const int h = pix >> 7, w = pix & 127;

    float kv[9];
    const float* kp = &g_ker[(size_t)pix * NOUT + cth];
    #pragma unroll
    for (int t = 0; t < 9; ++t) kv[t] = kp[t * CC];

    #pragma unroll
    for (int b = 0; b < BB; ++b) {
        float y = 0.0f;
        #pragma unroll
        for (int di = 0; di < 3; ++di) {
            int hh = h + di - 1;
            if ((unsigned)hh < (unsigned)HT) {
                const float* rowp = main_in + (((size_t)b * 64 + (hh >> 1)) * 64) * CC + cth;
                #pragma unroll
                for (int dj = 0; dj < 3; ++dj) {
                    int ww = w + dj - 1;
                    if ((unsigned)ww < (unsigned)HT)
                        y += rowp[(size_t)(ww >> 1) * CC] * kv[di * 3 + dj];
                }
            }
        }
        bf16 hi, lo; split_bf(y, hi, lo);
        size_t o = (size_t)(b * 16384 + pix) * CC + cth;
        g_yh[o] = hi; g_yl[o] = lo;
    }
}

// ---------------------------------------------------------------------------
// gemm2: out[65536,128] = y @ Wp + bp   (mma.sync bf16, split, K=256)
// grid 512; 256 thr = 8 warps (4m x 2n); CTA tile 128x128; k-chunks of 32
// ---------------------------------------------------------------------------
__global__ __launch_bounds__(256) void gemm2_kernel(const float* __restrict__ bp,
                                                    float* __restrict__ out)
{
    __shared__ __align__(16) bf16 As[128 * 72];
    __shared__ __align__(16) bf16 Bs[128 * 72];

    const int tid = threadIdx.x;
    const int wid = tid >> 5, lane = tid & 31;
    const int gid = lane >> 2, tig = lane & 3;
    const int m0 = blockIdx.x * 128;
    const int wm0 = (wid & 3) * 32, wn0 = (wid >> 2) * 64;

    float c[2][8][4];
    #pragma unroll
    for (int i = 0; i < 2; ++i)
        #pragma unroll
        for (int j = 0; j < 8; ++j)
            #pragma unroll
            for (int e = 0; e < 4; ++e) c[i][j][e] = 0.0f;

    for (int chunk = 0; chunk < 8; ++chunk) {
        const int kc = chunk * 32;
        __syncthreads();
        for (int i = tid; i < 512; i += 256) {
            int r = i >> 2, q = (i & 3) * 8;
            *(uint4*)&As[r * 72 + q]      = *(const uint4*)&g_yh[(size_t)(m0 + r) * CC + kc + q];
            *(uint4*)&As[r * 72 + 32 + q] = *(const uint4*)&g_yl[(size_t)(m0 + r) * CC + kc + q];
            *(uint4*)&Bs[r * 72 + q]      = *(const uint4*)&g_WpTh[(size_t)r * CC + kc + q];
            *(uint4*)&Bs[r * 72 + 32 + q] = *(const uint4*)&g_WpTl[(size_t)r * CC + kc + q];
        }
        __syncthreads();

        #pragma unroll
        for (int combo = 0; combo < 3; ++combo) {
            const int aoff = (combo == 2) ? 32 : 0;
            const int boff = (combo == 1) ? 32 : 0;
            #pragma unroll
            for (int ks = 0; ks < 2; ++ks) {
                const int kb = ks * 16;
                uint32_t a[2][4];
                #pragma unroll
                for (int mf = 0; mf < 2; ++mf) {
                    int row = wm0 + mf * 16 + gid;
                    a[mf][0] = *(const uint32_t*)&As[row * 72       + aoff + kb + tig * 2];
                    a[mf][1] = *(const uint32_t*)&As[(row + 8) * 72 + aoff + kb + tig * 2];
                    a[mf][2] = *(const uint32_t*)&As[row * 72       + aoff + kb + tig * 2 + 8];
                    a[mf][3] = *(const uint32_t*)&As[(row + 8) * 72 + aoff + kb + tig * 2 + 8];
                }
                uint32_t b[8][2];
                #pragma unroll
                for (int nf = 0; nf < 8; ++nf) {
                    int n = wn0 + nf * 8 + gid;
                    b[nf][0] = *(const uint32_t*)&Bs[n * 72 + boff + kb + tig * 2];
                    b[nf][1] = *(const uint32_t*)&Bs[n * 72 + boff + kb + tig * 2 + 8];
                }
                #pragma unroll
                for (int mf = 0; mf < 2; ++mf)
                    #pragma unroll
                    for (int nf = 0; nf < 8; ++nf)
                        mma16816(c[mf][nf], a[mf], b[nf]);
            }
        }
    }

    #pragma unroll
    for (int mf = 0; mf < 2; ++mf) {
        int gm = m0 + wm0 + mf * 16 + gid;
        #pragma unroll
        for (int nf = 0; nf < 8; ++nf) {
            int gn = wn0 + nf * 8 + tig * 2;
            float bx = __ldg(&bp[gn]), by = __ldg(&bp[gn + 1]);
            float2 v0 = { c[mf][nf][0] + bx, c[mf][nf][1] + by };
            float2 v1 = { c[mf][nf][2] + bx, c[mf][nf][3] + by };
            *(float2*)&out[(size_t)gm * FF + gn]       = v0;
            *(float2*)&out[(size_t)(gm + 8) * FF + gn] = v1;
        }
    }
}

// ---------------------------------------------------------------------------
extern "C" void kernel_launch(void* const* d_in, const int* in_sizes, int n_in,
                              void* d_out, int out_size)
{
    const float* main_in = (const float*)d_in[0];
    const float* W1 = (const float*)d_in[2];
    const float* b1 = (const float*)d_in[3];
    const float* W2 = (const float*)d_in[4];
    const float* b2 = (const float*)d_in[5];
    const float* W3 = (const float*)d_in[6];
    const float* b3 = (const float*)d_in[7];
    const float* W4 = (const float*)d_in[8];
    const float* b4 = (const float*)d_in[9];
    const float* Wo = (const float*)d_in[10];
    const float* bo = (const float*)d_in[11];
    const float* Wp = (const float*)d_in[12];
    const float* bp = (const float*)d_in[13];
    float* out = (float*)d_out;

    prep_kernel<<<(NOUT * 32 + FF * CC + 255) / 256, 256>>>(Wo, Wp);
    mlp_kernel<<<1024, 256>>>(W1, b1, W2, b2, W3, b3, W4, b4);
    gemm1_kernel<<<dim3(128, 18), 256>>>(bo);
    conv_kernel<<<16384, 256>>>(main_in);
    gemm2_kernel<<<512, 256>>>(bp, out);
}

// round 5
// speedup vs baseline: 2.0343x; 1.2558x over previous
#include <cuda_runtime.h>
#include <cuda_bf16.h>
#include <cstdint>
#include <math.h>

#define HT   128
#define CC   256
#define FF   128
#define BB   4
#define NU   32
#define NOUT 2304
#define NG   1024          // grouped hypernet output width (4 groups x 256)
#define PIF  3.14159265358979323846f

typedef __nv_bfloat16 bf16;

// ---------------- scratch globals ----------------
__device__ __align__(16) bf16  g_Wgh[4 * NG * 32];      // grouped Wo^T hi, [par][n][k]
__device__ __align__(16) bf16  g_Wgl[4 * NG * 32];
__device__ __align__(16) float g_bg[4 * NG];            // grouped bias, [par][n]
__device__ __align__(16) float g_Hc[128 * 32];          // layer1 h-partial
__device__ __align__(16) float g_Wc[128 * 32];          // layer1 w-partial
__device__ __align__(16) float g_Cc[32];                // layer1 const partial (incl b1)
__device__ __align__(16) bf16  g_x4h[(size_t)16384 * 32];  // [p'][k]
__device__ __align__(16) bf16  g_x4l[(size_t)16384 * 32];
__device__ __align__(16) bf16  g_WpTh[(size_t)FF * CC]; // [n][k]
__device__ __align__(16) bf16  g_WpTl[(size_t)FF * CC];
__device__ __align__(16) float g_ker2[(size_t)16384 * NG]; // 67 MB, [p'][g*256+c]
__device__ __align__(16) bf16  g_yh[(size_t)65536 * CC];
__device__ __align__(16) bf16  g_yl[(size_t)65536 * CC];

__device__ __forceinline__ void split_bf(float v, bf16& hi, bf16& lo) {
    hi = __float2bfloat16(v);
    lo = __float2bfloat16(v - __bfloat162float(hi));
}
__device__ __forceinline__ void mma16816(float c[4], const uint32_t a[4], const uint32_t b[2]) {
    asm volatile(
        "mma.sync.aligned.m16n8k16.row.col.f32.bf16.bf16.f32 "
        "{%0,%1,%2,%3}, {%4,%5,%6,%7}, {%8,%9}, {%0,%1,%2,%3};"
        : "+f"(c[0]), "+f"(c[1]), "+f"(c[2]), "+f"(c[3])
        : "r"(a[0]), "r"(a[1]), "r"(a[2]), "r"(a[3]), "r"(b[0]), "r"(b[1]));
}
// tap-row -> group (0 = row A = (h-1)>>1, 1 = row B = (h+1)>>1)
__device__ __forceinline__ int grp(int t, int par) { return (t == 0) ? 0 : (t == 2) ? 1 : (par ? 0 : 1); }

// ---------------------------------------------------------------------------
// prep: grouped Wo (hi/lo + bias), Wp^T hi/lo, layer1 partials
// ---------------------------------------------------------------------------
__global__ __launch_bounds__(256) void prep_kernel(
    const float* __restrict__ Wo, const float* __restrict__ bo,
    const float* __restrict__ Wp,
    const float* __restrict__ W1, const float* __restrict__ b1)
{
    int idx = blockIdx.x * 256 + threadIdx.x;
    if (idx < 4 * NG * 32) {                       // Wg
        int par = idx >> 15, rem = idx & 32767;
        int n = rem >> 5, k = rem & 31;
        int g = n >> 8, c = n & 255, gr = g >> 1, gc = g & 1;
        int ph = par >> 1, pw = par & 1;
        float s = 0.0f;
        #pragma unroll
        for (int tr = 0; tr < 3; ++tr)
            #pragma unroll
            for (int tc = 0; tc < 3; ++tc)
                if (grp(tr, ph) == gr && grp(tc, pw) == gc)
                    s += Wo[(size_t)k * NOUT + (tr * 3 + tc) * 256 + c];
        bf16 hi, lo; split_bf(s, hi, lo);
        g_Wgh[idx] = hi; g_Wgl[idx] = lo;
    } else if ((idx -= 4 * NG * 32) < 4 * NG) {    // bg
        int par = idx >> 10, n = idx & 1023;
        int g = n >> 8, c = n & 255, gr = g >> 1, gc = g & 1;
        int ph = par >> 1, pw = par & 1;
        float s = 0.0f;
        #pragma unroll
        for (int tr = 0; tr < 3; ++tr)
            #pragma unroll
            for (int tc = 0; tc < 3; ++tc)
                if (grp(tr, ph) == gr && grp(tc, pw) == gc)
                    s += bo[(tr * 3 + tc) * 256 + c];
        g_bg[idx] = s;
    } else if ((idx -= 4 * NG) < FF * CC) {        // WpT
        int n = idx >> 8, k = idx & 255;
        bf16 hi, lo; split_bf(Wp[(size_t)k * FF + n], hi, lo);
        g_WpTh[idx] = hi; g_WpTl[idx] = lo;
    } else if ((idx -= FF * CC) < 4096) {          // Hc
        int h = idx >> 5, j = idx & 31;
        float s = 0.0f;
        for (int i = 0; i < 25; ++i) {
            float f = 1.0f + (float)i * (1.0f / 24.0f);
            s += cosf(PIF * (2.0f * h * (1.0f / 127.0f) + 1.0f) * f) * W1[i * 32 + j];
        }
        g_Hc[idx] = s;
    } else if ((idx -= 4096) < 4096) {             // Wc
        int w = idx >> 5, j = idx & 31;
        float s = 0.0f;
        for (int i = 0; i < 25; ++i) {
            float f = 1.0f + (float)i * (1.0f / 24.0f);
            s += cosf(PIF * (2.0f * w * (1.0f / 127.0f) + 1.0f) * f) * W1[(25 + i) * 32 + j];
        }
        g_Wc[idx] = s;
    } else if ((idx -= 4096) < 32) {               // Cc
        int j = idx;
        float s = b1[j];
        for (int i = 0; i < 50; ++i) {
            float f = 1.0f + (float)(i % 25) * (1.0f / 24.0f);
            s += cosf(PIF * 5.0f * f) * W1[(50 + i) * 32 + j];
        }
        for (int i = 100; i < 118; ++i) s -= W1[i * 32 + j];
        g_Cc[j] = s;
    }
}

// ---------------------------------------------------------------------------
// mlp: layers 1-4 -> x4 hi/lo in parity-major p' order
// ---------------------------------------------------------------------------
__global__ __launch_bounds__(256) void mlp_kernel(
    const float* __restrict__ W2, const float* __restrict__ b2,
    const float* __restrict__ W3, const float* __restrict__ b3,
    const float* __restrict__ W4, const float* __restrict__ b4)
{
    __shared__ float xa[16][32];
    __shared__ float xb[16][32];
    const int tid = threadIdx.x;
    const int pix0 = blockIdx.x * 16;

    for (int o = tid; o < 512; o += 256) {
        int p = o >> 5, j = o & 31;
        int pix = pix0 + p, h = pix >> 7, w = pix & 127;
        float s = g_Hc[h * 32 + j] + g_Wc[w * 32 + j] + g_Cc[j];
        xa[p][j] = fmaxf(s, 0.0f);
    }
    __syncthreads();
    for (int o = tid; o < 512; o += 256) {
        int p = o >> 5, j = o & 31;
        float s = b2[j];
        #pragma unroll
        for (int k = 0; k < NU; ++k) s += xa[p][k] * W2[k * NU + j];
        xb[p][j] = fmaxf(s, 0.0f);
    }
    __syncthreads();
    for (int o = tid; o < 512; o += 256) {
        int p = o >> 5, j = o & 31;
        float s = b3[j];
        #pragma unroll
        for (int k = 0; k < NU; ++k) s += xb[p][k] * W3[k * NU + j];
        xa[p][j] = fmaxf(s, 0.0f);
    }
    __syncthreads();
    for (int o = tid; o < 512; o += 256) {
        int p = o >> 5, j = o & 31;
        float s = b4[j];
        #pragma unroll
        for (int k = 0; k < NU; ++k) s += xa[p][k] * W4[k * NU + j];
        float v = fmaxf(s, 0.0f);
        int pix = pix0 + p, h = pix >> 7, w = pix & 127;
        int pp = (((h & 1) << 1) | (w & 1)) * 4096 + (h >> 1) * 64 + (w >> 1);
        bf16 hi, lo; split_bf(v, hi, lo);
        size_t o2 = (size_t)pp * 32 + j;
        g_x4h[o2] = hi; g_x4l[o2] = lo;
    }
}

// ---------------------------------------------------------------------------
// gemm1: g_ker2[16384,1024] = x4 @ Wg[par] + bg[par]   (split-bf16 mma, K=32)
// grid (128, 8); m-tiles in p' space, parity = blockIdx.x>>5
// ---------------------------------------------------------------------------
__global__ __launch_bounds__(256) void gemm1_kernel()
{
    __shared__ __align__(16) bf16 As[128 * 72];
    __shared__ __align__(16) bf16 Bs[128 * 72];

    const int tid = threadIdx.x;
    const int wid = tid >> 5, lane = tid & 31;
    const int gid = lane >> 2, tig = lane & 3;
    const int m0 = blockIdx.x * 128, n0g = blockIdx.y * 128;
    const int par = blockIdx.x >> 5;
    const int wm0 = (wid & 3) * 32, wn0 = (wid >> 2) * 64;

    const bf16* WgH = g_Wgh + (size_t)par * NG * 32;
    const bf16* WgL = g_Wgl + (size_t)par * NG * 32;

    for (int i = tid; i < 512; i += 256) {
        int r = i >> 2, q = (i & 3) * 8;
        *(uint4*)&As[r * 72 + q]      = *(const uint4*)&g_x4h[(size_t)(m0 + r) * 32 + q];
        *(uint4*)&As[r * 72 + 32 + q] = *(const uint4*)&g_x4l[(size_t)(m0 + r) * 32 + q];
        *(uint4*)&Bs[r * 72 + q]      = *(const uint4*)&WgH[(size_t)(n0g + r) * 32 + q];
        *(uint4*)&Bs[r * 72 + 32 + q] = *(const uint4*)&WgL[(size_t)(n0g + r) * 32 + q];
    }
    __syncthreads();

    float c[2][8][4];
    #pragma unroll
    for (int i = 0; i < 2; ++i)
        #pragma unroll
        for (int j = 0; j < 8; ++j)
            #pragma unroll
            for (int e = 0; e < 4; ++e) c[i][j][e] = 0.0f;

    #pragma unroll
    for (int combo = 0; combo < 3; ++combo) {
        const int aoff = (combo == 2) ? 32 : 0;
        const int boff = (combo == 1) ? 32 : 0;
        #pragma unroll
        for (int ks = 0; ks < 2; ++ks) {
            const int kb = ks * 16;
            uint32_t a[2][4];
            #pragma unroll
            for (int mf = 0; mf < 2; ++mf) {
                int row = wm0 + mf * 16 + gid;
                a[mf][0] = *(const uint32_t*)&As[row * 72       + aoff + kb + tig * 2];
                a[mf][1] = *(const uint32_t*)&As[(row + 8) * 72 + aoff + kb + tig * 2];
                a[mf][2] = *(const uint32_t*)&As[row * 72       + aoff + kb + tig * 2 + 8];
                a[mf][3] = *(const uint32_t*)&As[(row + 8) * 72 + aoff + kb + tig * 2 + 8];
            }
            uint32_t b[8][2];
            #pragma unroll
            for (int nf = 0; nf < 8; ++nf) {
                int n = wn0 + nf * 8 + gid;
                b[nf][0] = *(const uint32_t*)&Bs[n * 72 + boff + kb + tig * 2];
                b[nf][1] = *(const uint32_t*)&Bs[n * 72 + boff + kb + tig * 2 + 8];
            }
            #pragma unroll
            for (int mf = 0; mf < 2; ++mf)
                #pragma unroll
                for (int nf = 0; nf < 8; ++nf)
                    mma16816(c[mf][nf], a[mf], b[nf]);
        }
    }

    const float* bgp = g_bg + par * NG;
    #pragma unroll
    for (int mf = 0; mf < 2; ++mf) {
        int gm = m0 + wm0 + mf * 16 + gid;
        #pragma unroll
        for (int nf = 0; nf < 8; ++nf) {
            int gn = n0g + wn0 + nf * 8 + tig * 2;
            float bx = __ldg(&bgp[gn]), by = __ldg(&bgp[gn + 1]);
            float2 v0 = { c[mf][nf][0] + bx, c[mf][nf][1] + by };
            float2 v1 = { c[mf][nf][2] + bx, c[mf][nf][3] + by };
            *(float2*)&g_ker2[(size_t)gm * NG + gn]       = v0;
            *(float2*)&g_ker2[(size_t)(gm + 8) * NG + gn] = v1;
        }
    }
}

// ---------------------------------------------------------------------------
// conv: 4-group weighted sum over 4 source pixels -> y bf16 hi/lo
// ---------------------------------------------------------------------------
__global__ __launch_bounds__(256) void conv_kernel(const float* __restrict__ main_in)
{
    const int pix = blockIdx.x, c = threadIdx.x;
    const int h = pix >> 7, w = pix & 127;
    const int par = ((h & 1) << 1) | (w & 1);

    const size_t kb = ((size_t)par * 4096 + (h >> 1) * 64 + (w >> 1)) * NG + c;
    const float k00 = g_ker2[kb];
    const float k01 = g_ker2[kb + 256];
    const float k10 = g_ker2[kb + 512];
    const float k11 = g_ker2[kb + 768];

    const int rA = (h - 1) >> 1, rB = (h + 1) >> 1;
    const int cA = (w - 1) >> 1, cB = (w + 1) >> 1;
    const bool vrA = h >= 1, vrB = h <= 126, vcA = w >= 1, vcB = w <= 126;

    #pragma unroll
    for (int b = 0; b < BB; ++b) {
        const float* base = main_in + (size_t)b * 64 * 64 * CC + c;
        float y = 0.0f;
        if (vrA) {
            const float* r = base + (size_t)rA * 64 * CC;
            if (vcA) y += k00 * r[(size_t)cA * CC];
            if (vcB) y += k01 * r[(size_t)cB * CC];
        }
        if (vrB) {
            const float* r = base + (size_t)rB * 64 * CC;
            if (vcA) y += k10 * r[(size_t)cA * CC];
            if (vcB) y += k11 * r[(size_t)cB * CC];
        }
        bf16 hi, lo; split_bf(y, hi, lo);
        size_t o = (size_t)(b * 16384 + pix) * CC + c;
        g_yh[o] = hi; g_yl[o] = lo;
    }
}

// ---------------------------------------------------------------------------
// gemm2: out[65536,128] = y @ Wp + bp   (split-bf16 mma, K=256)
// ---------------------------------------------------------------------------
__global__ __launch_bounds__(256) void gemm2_kernel(const float* __restrict__ bp,
                                                    float* __restrict__ out)
{
    __shared__ __align__(16) bf16 As[128 * 72];
    __shared__ __align__(16) bf16 Bs[128 * 72];

    const int tid = threadIdx.x;
    const int wid = tid >> 5, lane = tid & 31;
    const int gid = lane >> 2, tig = lane & 3;
    const int m0 = blockIdx.x * 128;
    const int wm0 = (wid & 3) * 32, wn0 = (wid >> 2) * 64;

    float c[2][8][4];
    #pragma unroll
    for (int i = 0; i < 2; ++i)
        #pragma unroll
        for (int j = 0; j < 8; ++j)
            #pragma unroll
            for (int e = 0; e < 4; ++e) c[i][j][e] = 0.0f;

    for (int chunk = 0; chunk < 8; ++chunk) {
        const int kc = chunk * 32;
        __syncthreads();
        for (int i = tid; i < 512; i += 256) {
            int r = i >> 2, q = (i & 3) * 8;
            *(uint4*)&As[r * 72 + q]      = *(const uint4*)&g_yh[(size_t)(m0 + r) * CC + kc + q];
            *(uint4*)&As[r * 72 + 32 + q] = *(const uint4*)&g_yl[(size_t)(m0 + r) * CC + kc + q];
            *(uint4*)&Bs[r * 72 + q]      = *(const uint4*)&g_WpTh[(size_t)r * CC + kc + q];
            *(uint4*)&Bs[r * 72 + 32 + q] = *(const uint4*)&g_WpTl[(size_t)r * CC + kc + q];
        }
        __syncthreads();

        #pragma unroll
        for (int combo = 0; combo < 3; ++combo) {
            const int aoff = (combo == 2) ? 32 : 0;
            const int boff = (combo == 1) ? 32 : 0;
            #pragma unroll
            for (int ks = 0; ks < 2; ++ks) {
                const int kb = ks * 16;
                uint32_t a[2][4];
                #pragma unroll
                for (int mf = 0; mf < 2; ++mf) {
                    int row = wm0 + mf * 16 + gid;
                    a[mf][0] = *(const uint32_t*)&As[row * 72       + aoff + kb + tig * 2];
                    a[mf][1] = *(const uint32_t*)&As[(row + 8) * 72 + aoff + kb + tig * 2];
                    a[mf][2] = *(const uint32_t*)&As[row * 72       + aoff + kb + tig * 2 + 8];
                    a[mf][3] = *(const uint32_t*)&As[(row + 8) * 72 + aoff + kb + tig * 2 + 8];
                }
                uint32_t b[8][2];
                #pragma unroll
                for (int nf = 0; nf < 8; ++nf) {
                    int n = wn0 + nf * 8 + gid;
                    b[nf][0] = *(const uint32_t*)&Bs[n * 72 + boff + kb + tig * 2];
                    b[nf][1] = *(const uint32_t*)&Bs[n * 72 + boff + kb + tig * 2 + 8];
                }
                #pragma unroll
                for (int mf = 0; mf < 2; ++mf)
                    #pragma unroll
                    for (int nf = 0; nf < 8; ++nf)
                        mma16816(c[mf][nf], a[mf], b[nf]);
            }
        }
    }

    #pragma unroll
    for (int mf = 0; mf < 2; ++mf) {
        int gm = m0 + wm0 + mf * 16 + gid;
        #pragma unroll
        for (int nf = 0; nf < 8; ++nf) {
            int gn = wn0 + nf * 8 + tig * 2;
            float bx = __ldg(&bp[gn]), by = __ldg(&bp[gn + 1]);
            float2 v0 = { c[mf][nf][0] + bx, c[mf][nf][1] + by };
            float2 v1 = { c[mf][nf][2] + bx, c[mf][nf][3] + by };
            *(float2*)&out[(size_t)gm * FF + gn]       = v0;
            *(float2*)&out[(size_t)(gm + 8) * FF + gn] = v1;
        }
    }
}

// ---------------------------------------------------------------------------
extern "C" void kernel_launch(void* const* d_in, const int* in_sizes, int n_in,
                              void* d_out, int out_size)
{
    const float* main_in = (const float*)d_in[0];
    const float* W1 = (const float*)d_in[2];
    const float* b1 = (const float*)d_in[3];
    const float* W2 = (const float*)d_in[4];
    const float* b2 = (const float*)d_in[5];
    const float* W3 = (const float*)d_in[6];
    const float* b3 = (const float*)d_in[7];
    const float* W4 = (const float*)d_in[8];
    const float* b4 = (const float*)d_in[9];
    const float* Wo = (const float*)d_in[10];
    const float* bo = (const float*)d_in[11];
    const float* Wp = (const float*)d_in[12];
    const float* bp = (const float*)d_in[13];
    float* out = (float*)d_out;

    const int prep_elems = 4 * NG * 32 + 4 * NG + FF * CC + 4096 + 4096 + 32;
    prep_kernel<<<(prep_elems + 255) / 256, 256>>>(Wo, bo, Wp, W1, b1);
    mlp_kernel<<<1024, 256>>>(W2, b2, W3, b3, W4, b4);
    gemm1_kernel<<<dim3(128, 8), 256>>>();
    conv_kernel<<<16384, 256>>>(main_in);
    gemm2_kernel<<<512, 256>>>(bp, out);
}